// round 5
// baseline (speedup 1.0000x reference)
#include <cuda_runtime.h>
#include <cuda_bf16.h>

#define Bsz 2
#define Nv  4096
#define Me  12288

// ---- scratch layout (floats) ----
#define OFF_WT 0LL               // 5 * 65536
#define OFF_VQ 327680LL          // 2*4096*256 each
#define OFF_VK 2424832LL
#define OFF_VV 4521984LL
#define OFF_EQ 6619136LL         // 2*12288*256 each
#define OFF_EK 12910592LL
#define OFF_X1 19202048LL
#define OFF_X2 25493504LL
#define OFF_X3 31784960LL
__device__ float g_scratch[33882112];

// ---------------- helpers ----------------
__device__ __forceinline__ float f2tf32(float x) {
    unsigned u;
    asm("cvt.rna.tf32.f32 %0, %1;" : "=r"(u) : "f"(x));
    return __uint_as_float(u);
}
__device__ __forceinline__ void mma8(float* c, const float* ah, const float* bh) {
    asm volatile(
        "mma.sync.aligned.m16n8k8.row.col.f32.tf32.tf32.f32 "
        "{%0,%1,%2,%3},{%4,%5,%6,%7},{%8,%9},{%0,%1,%2,%3};\n"
        : "+f"(c[0]), "+f"(c[1]), "+f"(c[2]), "+f"(c[3])
        : "r"(__float_as_uint(ah[0])), "r"(__float_as_uint(ah[1])),
          "r"(__float_as_uint(ah[2])), "r"(__float_as_uint(ah[3])),
          "r"(__float_as_uint(bh[0])), "r"(__float_as_uint(bh[1])));
}

// ---------------- 256x256 transpose: Wt[d][e] = W[e][d] ----------------
__global__ void transpose256(const float* __restrict__ W, float* __restrict__ Wt) {
    __shared__ float t[32][33];
    int bx = blockIdx.x * 32, by = blockIdx.y * 32;
    int tx = threadIdx.x, ty = threadIdx.y;
#pragma unroll
    for (int j = 0; j < 32; j += 8) t[ty + j][tx] = W[(by + ty + j) * 256 + bx + tx];
    __syncthreads();
#pragma unroll
    for (int j = 0; j < 32; j += 8) Wt[(bx + ty + j) * 256 + by + tx] = t[tx][ty + j];
}

// ---------------- GEMM: C[Mr x 256] = op(A)[Mr x K] @ Bm[K x 256] ----------------
// TRANSA=0: A(i,k)=A[i*lda+k]; TRANSA=1: A(i,k)=A[k*lda+i]. tf32 3-mma split.
template <bool TRANSA>
__global__ void __launch_bounds__(256) gemm_tf32(
    const float* __restrict__ A, const float* __restrict__ Bm, float* __restrict__ C,
    int K, int lda, long long sA, long long sB, long long sC)
{
    __shared__ float As[16][72];    // [k][m]
    __shared__ float Bs[16][136];   // [k][n]
    const int bm = blockIdx.x * 64;
    const int bn = blockIdx.y * 128;
    A += (long long)blockIdx.z * sA;
    Bm += (long long)blockIdx.z * sB;
    C += (long long)blockIdx.z * sC;

    const int tid = threadIdx.x;
    const int warp = tid >> 5, lane = tid & 31;
    const int g = lane >> 2, t = lane & 3;
    const int wm = (warp & 1) * 32, wn = (warp >> 1) * 32;

    float acc[2][4][4];
#pragma unroll
    for (int i = 0; i < 2; i++)
#pragma unroll
        for (int j = 0; j < 4; j++)
#pragma unroll
            for (int r = 0; r < 4; r++) acc[i][j][r] = 0.f;

    for (int kk = 0; kk < K; kk += 16) {
        // --- load A tile ---
        if (!TRANSA) {
            int m = tid >> 2, kq = tid & 3;
            float4 v = *(const float4*)(A + (long long)(bm + m) * lda + kk + kq * 4);
            As[kq * 4 + 0][m] = v.x; As[kq * 4 + 1][m] = v.y;
            As[kq * 4 + 2][m] = v.z; As[kq * 4 + 3][m] = v.w;
        } else {
            int k = tid >> 4, i4 = tid & 15;
            float4 v = *(const float4*)(A + (long long)(kk + k) * lda + bm + i4 * 4);
            *(float4*)&As[k][i4 * 4] = v;
        }
        // --- load B tile (row length 256 always) ---
#pragma unroll
        for (int r = 0; r < 2; r++) {
            int idx = tid + 256 * r;
            int k = idx >> 5, n4 = idx & 31;
            float4 v = *(const float4*)(Bm + (long long)(kk + k) * 256 + bn + n4 * 4);
            *(float4*)&Bs[k][n4 * 4] = v;
        }
        __syncthreads();

#pragma unroll
        for (int ks = 0; ks < 2; ks++) {
            int k0 = ks * 8;
            float ah[2][4], al[2][4];
#pragma unroll
            for (int mt = 0; mt < 2; mt++) {
                int mb = wm + mt * 16;
                float r0 = As[k0 + t][mb + g];
                float r1 = As[k0 + t][mb + g + 8];
                float r2 = As[k0 + t + 4][mb + g];
                float r3 = As[k0 + t + 4][mb + g + 8];
                ah[mt][0] = f2tf32(r0); al[mt][0] = f2tf32(r0 - ah[mt][0]);
                ah[mt][1] = f2tf32(r1); al[mt][1] = f2tf32(r1 - ah[mt][1]);
                ah[mt][2] = f2tf32(r2); al[mt][2] = f2tf32(r2 - ah[mt][2]);
                ah[mt][3] = f2tf32(r3); al[mt][3] = f2tf32(r3 - ah[mt][3]);
            }
            float bh[4][2], bl[4][2];
#pragma unroll
            for (int nt = 0; nt < 4; nt++) {
                int nb = wn + nt * 8 + g;
                float r0 = Bs[k0 + t][nb];
                float r1 = Bs[k0 + t + 4][nb];
                bh[nt][0] = f2tf32(r0); bl[nt][0] = f2tf32(r0 - bh[nt][0]);
                bh[nt][1] = f2tf32(r1); bl[nt][1] = f2tf32(r1 - bh[nt][1]);
            }
#pragma unroll
            for (int mt = 0; mt < 2; mt++)
#pragma unroll
                for (int nt = 0; nt < 4; nt++) {
                    mma8(acc[mt][nt], ah[mt], bh[nt]);
                    mma8(acc[mt][nt], ah[mt], bl[nt]);
                    mma8(acc[mt][nt], al[mt], bh[nt]);
                }
        }
        __syncthreads();
    }

    // --- epilogue ---
#pragma unroll
    for (int mt = 0; mt < 2; mt++) {
        int row0 = bm + wm + mt * 16 + g;
#pragma unroll
        for (int nt = 0; nt < 4; nt++) {
            int col = bn + wn + nt * 8 + 2 * t;
            float2 v0 = make_float2(acc[mt][nt][0], acc[mt][nt][1]);
            float2 v1 = make_float2(acc[mt][nt][2], acc[mt][nt][3]);
            *(float2*)(C + (long long)row0 * 256 + col) = v0;
            *(float2*)(C + (long long)(row0 + 8) * 256 + col) = v1;
        }
    }
}

// ---------------- per-head (32-dim) LayerNorm, in place ----------------
__global__ void ln_k(float* __restrict__ X) {
    long long row = blockIdx.x;
    int tx = threadIdx.x;
    float v = X[row * 256 + tx];
    float s = v;
#pragma unroll
    for (int o = 16; o; o >>= 1) s += __shfl_xor_sync(0xffffffffu, s, o);
    float mu = s * (1.f / 32.f);
    float d = v - mu;
    float q = d * d;
#pragma unroll
    for (int o = 16; o; o >>= 1) q += __shfl_xor_sync(0xffffffffu, q, o);
    X[row * 256 + tx] = d * rsqrtf(q * (1.f / 32.f) + 1e-5f);
}

// ---------------- sparse attention ----------------
// out[b,r,h,:] = softmax_j( q[b,r,h,:].k[b,idx[r,j],h,:]/sqrt(32) ) . x[b,idx[r,j],h,:]
__global__ void sattn_k(const float* __restrict__ q, const float* __restrict__ k,
                        const float* __restrict__ x, const int* __restrict__ idx,
                        float* __restrict__ out, int R)
{
    int r = blockIdx.x;
    long long boff = (long long)blockIdx.y * R * 256;
    int h = threadIdx.x >> 5, lane = threadIdx.x & 31;
    __shared__ int sidx[16];
    if (threadIdx.x < 16) sidx[threadIdx.x] = idx[r * 16 + threadIdx.x];
    float qv = q[boff + (long long)r * 256 + h * 32 + lane];
    __syncthreads();

    float s[16];
#pragma unroll
    for (int j = 0; j < 16; j++) {
        float p = qv * k[boff + (long long)sidx[j] * 256 + h * 32 + lane];
#pragma unroll
        for (int o = 16; o; o >>= 1) p += __shfl_xor_sync(0xffffffffu, p, o);
        s[j] = p * 0.17677669529663687f;  // 1/sqrt(32)
    }
    float mx = s[0];
#pragma unroll
    for (int j = 1; j < 16; j++) mx = fmaxf(mx, s[j]);
    float se = 0.f;
#pragma unroll
    for (int j = 0; j < 16; j++) { s[j] = __expf(s[j] - mx); se += s[j]; }
    float inv = 1.f / se;
    float acc = 0.f;
#pragma unroll
    for (int j = 0; j < 16; j++)
        acc += s[j] * x[boff + (long long)sidx[j] * 256 + h * 32 + lane];
    out[boff + (long long)r * 256 + h * 32 + lane] = acc * inv;
}

// ---------------- host ----------------
extern "C" void kernel_launch(void* const* d_in, const int* in_sizes, int n_in,
                              void* d_out, int out_size) {
    const float* x_v = (const float*)d_in[0];
    const float* x_e = (const float*)d_in[1];
    const float* d0  = (const float*)d_in[2];
    const int* v_idx = (const int*)d_in[8];
    const int* e_idx = (const int*)d_in[9];
    float* out = (float*)d_out;

    float* S = nullptr;
    cudaGetSymbolAddress((void**)&S, g_scratch);
    float* WT = S + OFF_WT;
    float* VQ = S + OFF_VQ; float* VK = S + OFF_VK; float* VV = S + OFF_VV;
    float* EQ = S + OFF_EQ; float* EK = S + OFF_EK;
    float* X1 = S + OFF_X1; float* X2 = S + OFF_X2; float* X3 = S + OFF_X3;

    // 1) transpose the 5 weight matrices
    dim3 tb(32, 8), tg(8, 8);
    for (int i = 0; i < 5; i++)
        transpose256<<<tg, tb>>>((const float*)d_in[3 + i], WT + (long long)i * 65536);

    // 2) projections (batch-merged rows): rows_v = 8192, rows_e = 24576
    {
        dim3 gv(8192 / 64, 2, 1), ge(24576 / 64, 2, 1);
        gemm_tf32<false><<<gv, 256>>>(x_v, WT + 0 * 65536, VQ, 256, 256, 0, 0, 0);
        gemm_tf32<false><<<gv, 256>>>(x_v, WT + 1 * 65536, VK, 256, 256, 0, 0, 0);
        gemm_tf32<false><<<gv, 256>>>(x_v, WT + 2 * 65536, VV, 256, 256, 0, 0, 0);
        gemm_tf32<false><<<ge, 256>>>(x_e, WT + 3 * 65536, EQ, 256, 256, 0, 0, 0);
        gemm_tf32<false><<<ge, 256>>>(x_e, WT + 4 * 65536, EK, 256, 256, 0, 0, 0);
    }

    // 3) per-head layernorms
    ln_k<<<8192, 256>>>(VQ);
    ln_k<<<8192, 256>>>(VK);
    ln_k<<<24576, 256>>>(EQ);
    ln_k<<<24576, 256>>>(EK);

    // 4) X1[b] = d0[b] @ VV[b]   (12288 x 4096 x 256)
    {
        dim3 g(Me / 64, 2, Bsz);
        gemm_tf32<false><<<g, 256>>>(d0, VV, X1, Nv, Nv,
                                     (long long)Me * Nv, (long long)Nv * 256, (long long)Me * 256);
    }

    // 5) X2 = sparse_attention(X1, EQ, EK, e_idx)
    sattn_k<<<dim3(Me, Bsz), 256>>>(EQ, EK, X1, e_idx, X2, Me);

    // 6) X3[b] = d0[b]^T @ X2[b]   (4096 x 12288 x 256)
    {
        dim3 g(Nv / 64, 2, Bsz);
        gemm_tf32<true><<<g, 256>>>(d0, X2, X3, Me, Nv,
                                    (long long)Me * Nv, (long long)Me * 256, (long long)Nv * 256);
    }

    // 7) out = sparse_attention(X3, VK, VQ, v_idx)  -> (B, N, 256)
    sattn_k<<<dim3(Nv, Bsz), 256>>>(VK, VQ, X3, v_idx, out, Nv);
}

// round 6
// speedup vs baseline: 1.8798x; 1.8798x over previous
#include <cuda_runtime.h>
#include <cuda_bf16.h>

#define Bsz 2
#define Nv  4096
#define Me  12288

// ---- scratch layout (floats) ----
#define OFF_WT 0LL               // 5 * 65536
#define OFF_VQ 327680LL          // 2*4096*256 each
#define OFF_VK 2424832LL
#define OFF_VV 4521984LL
#define OFF_EQ 6619136LL         // 2*12288*256 each
#define OFF_EK 12910592LL
#define OFF_X1 19202048LL
#define OFF_X2 25493504LL
#define OFF_X3 31784960LL
__device__ float g_scratch[33882112];

// ---------------- low-level helpers ----------------
__device__ __forceinline__ unsigned cvta_s(const void* p) {
    return (unsigned)__cvta_generic_to_shared(p);
}
__device__ __forceinline__ void ldm_x4(unsigned* r, unsigned addr) {
    asm volatile("ldmatrix.sync.aligned.m8n8.x4.shared.b16 {%0,%1,%2,%3},[%4];"
                 : "=r"(r[0]), "=r"(r[1]), "=r"(r[2]), "=r"(r[3]) : "r"(addr));
}
__device__ __forceinline__ void ldm_x4_t(unsigned* r, unsigned addr) {
    asm volatile("ldmatrix.sync.aligned.m8n8.x4.trans.shared.b16 {%0,%1,%2,%3},[%4];"
                 : "=r"(r[0]), "=r"(r[1]), "=r"(r[2]), "=r"(r[3]) : "r"(addr));
}
__device__ __forceinline__ void mma16(float* c, const unsigned* a, const unsigned* b) {
    asm volatile(
        "mma.sync.aligned.m16n8k16.row.col.f32.bf16.bf16.f32 "
        "{%0,%1,%2,%3},{%4,%5,%6,%7},{%8,%9},{%0,%1,%2,%3};\n"
        : "+f"(c[0]), "+f"(c[1]), "+f"(c[2]), "+f"(c[3])
        : "r"(a[0]), "r"(a[1]), "r"(a[2]), "r"(a[3]), "r"(b[0]), "r"(b[1]));
}
// split a float4 into hi/lo bf16x2 pairs (halves packed along the vector dim)
__device__ __forceinline__ void cvt_split4(float4 v, uint2& hi, uint2& lo) {
    __nv_bfloat162 h0 = __floats2bfloat162_rn(v.x, v.y);
    __nv_bfloat162 h1 = __floats2bfloat162_rn(v.z, v.w);
    float2 f0 = __bfloat1622float2(h0);
    float2 f1 = __bfloat1622float2(h1);
    __nv_bfloat162 l0 = __floats2bfloat162_rn(v.x - f0.x, v.y - f0.y);
    __nv_bfloat162 l1 = __floats2bfloat162_rn(v.z - f1.x, v.w - f1.y);
    hi.x = *(unsigned*)&h0; hi.y = *(unsigned*)&h1;
    lo.x = *(unsigned*)&l0; lo.y = *(unsigned*)&l1;
}

// ---------------- 256x256 transpose: Wt[d][e] = W[e][d] ----------------
__global__ void transpose256(const float* __restrict__ W, float* __restrict__ Wt) {
    __shared__ float t[32][33];
    int bx = blockIdx.x * 32, by = blockIdx.y * 32;
    int tx = threadIdx.x, ty = threadIdx.y;
#pragma unroll
    for (int j = 0; j < 32; j += 8) t[ty + j][tx] = W[(by + ty + j) * 256 + bx + tx];
    __syncthreads();
#pragma unroll
    for (int j = 0; j < 32; j += 8) Wt[(bx + ty + j) * 256 + by + tx] = t[tx][ty + j];
}

// ---------------- GEMM: C[Mr x 256] = op(A)[Mr x K] @ Bm[K x 256] ----------------
// bf16 3-mma split (hi*hi + hi*lo + lo*hi), tile 64 x 256 x 16, double-buffered.
// TRANSA=0: A(i,k)=A[i*lda+k]; TRANSA=1: A(i,k)=A[k*lda+i].
template <bool TRANSA>
__global__ void __launch_bounds__(256, 2) gemm_bf16s(
    const float* __restrict__ A, const float* __restrict__ Bm, float* __restrict__ C,
    int K, int lda, long long sA, long long sB, long long sC)
{
    constexpr int A_SZ = 1536;       // halves per A buffer (max of both layouts)
    constexpr int B_SZ = 16 * 264;   // halves per B buffer
    __shared__ __align__(16) __nv_bfloat16 Ah[2][A_SZ], Al[2][A_SZ];
    __shared__ __align__(16) __nv_bfloat16 Bh[2][B_SZ], Bl[2][B_SZ];

    const int bm = blockIdx.x * 64;
    A  += (long long)blockIdx.z * sA;
    Bm += (long long)blockIdx.z * sB;
    C  += (long long)blockIdx.z * sC;

    const int tid = threadIdx.x, warp = tid >> 5, lane = tid & 31;
    const int g = lane >> 2, t = lane & 3;
    const int wm = (warp & 1) * 32, wn = (warp >> 1) * 64;
    const int o = lane >> 3, i8 = lane & 7;

    // ldmatrix byte offsets within a buffer
    int offA0;
    if (!TRANSA) {
        // As[m][24 halves]: rows m0..m0+7 / +8 (o&1), k col 0/8 (o>>1)
        int row = wm + ((o & 1) << 3) + i8;
        int col = (o >> 1) << 3;
        offA0 = row * 48 + col * 2;            // mt step = 16 rows = 768 B
    } else {
        // As[k][72 halves]: k = (o>>1)*8 + i8 ; m = wm + (o&1)*8
        int k = ((o >> 1) << 3) + i8;
        int m = wm + ((o & 1) << 3);
        offA0 = k * 144 + m * 2;               // mt step = 16 halves = 32 B
    }
    const int offB0 = (((o & 1) << 3) + i8) * 528 + (wn + ((o >> 1) << 3)) * 2; // np step 32 B

    const unsigned baseAh = cvta_s(Ah), baseAl = cvta_s(Al);
    const unsigned baseBh = cvta_s(Bh), baseBl = cvta_s(Bl);

    float acc[2][8][4];
#pragma unroll
    for (int a = 0; a < 2; a++)
#pragma unroll
        for (int b = 0; b < 8; b++)
#pragma unroll
            for (int c = 0; c < 4; c++) acc[a][b][c] = 0.f;

    // staging registers
    float4 ra, rb0, rb1, rb2, rb3;
    const int am = tid >> 2, akq = tid & 3;     // !TRANSA A indexing
    const int ak = tid >> 4, ai4 = tid & 15;    // TRANSA A indexing
    const int bk = tid >> 6, bn4 = tid & 63;    // B indexing (4 k rows apart)

    auto ldg_tile = [&](int kk) {
        if (!TRANSA)
            ra = *(const float4*)(A + (long long)(bm + am) * lda + kk + 4 * akq);
        else
            ra = *(const float4*)(A + (long long)(kk + ak) * lda + bm + 4 * ai4);
        const float* bp = Bm + (long long)kk * 256 + 4 * bn4;
        rb0 = *(const float4*)(bp + (long long)(bk)      * 256);
        rb1 = *(const float4*)(bp + (long long)(bk + 4)  * 256);
        rb2 = *(const float4*)(bp + (long long)(bk + 8)  * 256);
        rb3 = *(const float4*)(bp + (long long)(bk + 12) * 256);
    };
    auto sts_tile = [&](int buf) {
        uint2 hi, lo;
        cvt_split4(ra, hi, lo);
        if (!TRANSA) {
            *(uint2*)&Ah[buf][am * 24 + 4 * akq] = hi;
            *(uint2*)&Al[buf][am * 24 + 4 * akq] = lo;
        } else {
            *(uint2*)&Ah[buf][ak * 72 + 4 * ai4] = hi;
            *(uint2*)&Al[buf][ak * 72 + 4 * ai4] = lo;
        }
        cvt_split4(rb0, hi, lo);
        *(uint2*)&Bh[buf][(bk)      * 264 + 4 * bn4] = hi;
        *(uint2*)&Bl[buf][(bk)      * 264 + 4 * bn4] = lo;
        cvt_split4(rb1, hi, lo);
        *(uint2*)&Bh[buf][(bk + 4)  * 264 + 4 * bn4] = hi;
        *(uint2*)&Bl[buf][(bk + 4)  * 264 + 4 * bn4] = lo;
        cvt_split4(rb2, hi, lo);
        *(uint2*)&Bh[buf][(bk + 8)  * 264 + 4 * bn4] = hi;
        *(uint2*)&Bl[buf][(bk + 8)  * 264 + 4 * bn4] = lo;
        cvt_split4(rb3, hi, lo);
        *(uint2*)&Bh[buf][(bk + 12) * 264 + 4 * bn4] = hi;
        *(uint2*)&Bl[buf][(bk + 12) * 264 + 4 * bn4] = lo;
    };

    const int KT = K >> 4;
    ldg_tile(0);
    sts_tile(0);
    __syncthreads();

    int buf = 0;
    for (int kt = 0; kt < KT; kt++) {
        if (kt + 1 < KT) ldg_tile((kt + 1) << 4);

        // fragments for this tile
        const unsigned aoffs = buf * (A_SZ * 2);
        const unsigned boffs = buf * (B_SZ * 2);
        unsigned Ahr[2][4], Alr[2][4];
#pragma unroll
        for (int mt = 0; mt < 2; mt++) {
            const int mstep = TRANSA ? 32 : 768;
            if (!TRANSA) {
                ldm_x4(Ahr[mt], baseAh + aoffs + offA0 + mt * mstep);
                ldm_x4(Alr[mt], baseAl + aoffs + offA0 + mt * mstep);
            } else {
                ldm_x4_t(Ahr[mt], baseAh + aoffs + offA0 + mt * mstep);
                ldm_x4_t(Alr[mt], baseAl + aoffs + offA0 + mt * mstep);
            }
        }
#pragma unroll
        for (int np = 0; np < 4; np++) {
            unsigned bh[4], bl[4];
            ldm_x4_t(bh, baseBh + boffs + offB0 + np * 32);
            ldm_x4_t(bl, baseBl + boffs + offB0 + np * 32);
#pragma unroll
            for (int mt = 0; mt < 2; mt++)
#pragma unroll
                for (int j = 0; j < 2; j++) {
                    float* c = acc[mt][2 * np + j];
                    mma16(c, Ahr[mt], bh + 2 * j);
                    mma16(c, Ahr[mt], bl + 2 * j);
                    mma16(c, Alr[mt], bh + 2 * j);
                }
        }

        if (kt + 1 < KT) sts_tile(buf ^ 1);
        __syncthreads();
        buf ^= 1;
    }

    // epilogue
#pragma unroll
    for (int mt = 0; mt < 2; mt++) {
        int row0 = bm + wm + mt * 16 + g;
#pragma unroll
        for (int nt = 0; nt < 8; nt++) {
            int col = wn + nt * 8 + 2 * t;
            float2 v0 = make_float2(acc[mt][nt][0], acc[mt][nt][1]);
            float2 v1 = make_float2(acc[mt][nt][2], acc[mt][nt][3]);
            *(float2*)(C + (long long)row0 * 256 + col) = v0;
            *(float2*)(C + (long long)(row0 + 8) * 256 + col) = v1;
        }
    }
}

// ---------------- per-head (32-dim) LayerNorm, in place ----------------
__global__ void ln_k(float* __restrict__ X) {
    long long row = blockIdx.x;
    int tx = threadIdx.x;
    float v = X[row * 256 + tx];
    float s = v;
#pragma unroll
    for (int o = 16; o; o >>= 1) s += __shfl_xor_sync(0xffffffffu, s, o);
    float mu = s * (1.f / 32.f);
    float d = v - mu;
    float q = d * d;
#pragma unroll
    for (int o = 16; o; o >>= 1) q += __shfl_xor_sync(0xffffffffu, q, o);
    X[row * 256 + tx] = d * rsqrtf(q * (1.f / 32.f) + 1e-5f);
}

// ---------------- sparse attention ----------------
__global__ void sattn_k(const float* __restrict__ q, const float* __restrict__ k,
                        const float* __restrict__ x, const int* __restrict__ idx,
                        float* __restrict__ out, int R)
{
    int r = blockIdx.x;
    long long boff = (long long)blockIdx.y * R * 256;
    int h = threadIdx.x >> 5, lane = threadIdx.x & 31;
    __shared__ int sidx[16];
    if (threadIdx.x < 16) sidx[threadIdx.x] = idx[r * 16 + threadIdx.x];
    float qv = q[boff + (long long)r * 256 + h * 32 + lane];
    __syncthreads();

    float s[16];
#pragma unroll
    for (int j = 0; j < 16; j++) {
        float p = qv * k[boff + (long long)sidx[j] * 256 + h * 32 + lane];
#pragma unroll
        for (int o = 16; o; o >>= 1) p += __shfl_xor_sync(0xffffffffu, p, o);
        s[j] = p * 0.17677669529663687f;  // 1/sqrt(32)
    }
    float mx = s[0];
#pragma unroll
    for (int j = 1; j < 16; j++) mx = fmaxf(mx, s[j]);
    float se = 0.f;
#pragma unroll
    for (int j = 0; j < 16; j++) { s[j] = __expf(s[j] - mx); se += s[j]; }
    float inv = 1.f / se;
    float acc = 0.f;
#pragma unroll
    for (int j = 0; j < 16; j++)
        acc += s[j] * x[boff + (long long)sidx[j] * 256 + h * 32 + lane];
    out[boff + (long long)r * 256 + h * 32 + lane] = acc * inv;
}

// ---------------- host ----------------
extern "C" void kernel_launch(void* const* d_in, const int* in_sizes, int n_in,
                              void* d_out, int out_size) {
    const float* x_v = (const float*)d_in[0];
    const float* x_e = (const float*)d_in[1];
    const float* d0  = (const float*)d_in[2];
    const int* v_idx = (const int*)d_in[8];
    const int* e_idx = (const int*)d_in[9];
    float* out = (float*)d_out;

    float* S = nullptr;
    cudaGetSymbolAddress((void**)&S, g_scratch);
    float* WT = S + OFF_WT;
    float* VQ = S + OFF_VQ; float* VK = S + OFF_VK; float* VV = S + OFF_VV;
    float* EQ = S + OFF_EQ; float* EK = S + OFF_EK;
    float* X1 = S + OFF_X1; float* X2 = S + OFF_X2; float* X3 = S + OFF_X3;

    // 1) transpose the 5 weight matrices
    dim3 tb(32, 8), tg(8, 8);
    for (int i = 0; i < 5; i++)
        transpose256<<<tg, tb>>>((const float*)d_in[3 + i], WT + (long long)i * 65536);

    // 2) projections (batch-merged rows): rows_v = 8192, rows_e = 24576
    {
        dim3 gv(8192 / 64, 1, 1), ge(24576 / 64, 1, 1);
        gemm_bf16s<false><<<gv, 256>>>(x_v, WT + 0 * 65536, VQ, 256, 256, 0, 0, 0);
        gemm_bf16s<false><<<gv, 256>>>(x_v, WT + 1 * 65536, VK, 256, 256, 0, 0, 0);
        gemm_bf16s<false><<<gv, 256>>>(x_v, WT + 2 * 65536, VV, 256, 256, 0, 0, 0);
        gemm_bf16s<false><<<ge, 256>>>(x_e, WT + 3 * 65536, EQ, 256, 256, 0, 0, 0);
        gemm_bf16s<false><<<ge, 256>>>(x_e, WT + 4 * 65536, EK, 256, 256, 0, 0, 0);
    }

    // 3) per-head layernorms
    ln_k<<<8192, 256>>>(VQ);
    ln_k<<<8192, 256>>>(VK);
    ln_k<<<24576, 256>>>(EQ);
    ln_k<<<24576, 256>>>(EK);

    // 4) X1[b] = d0[b] @ VV[b]   (12288 x 4096 x 256)
    {
        dim3 g(Me / 64, 1, Bsz);
        gemm_bf16s<false><<<g, 256>>>(d0, VV, X1, Nv, Nv,
                                      (long long)Me * Nv, (long long)Nv * 256, (long long)Me * 256);
    }

    // 5) X2 = sparse_attention(X1, EQ, EK, e_idx)
    sattn_k<<<dim3(Me, Bsz), 256>>>(EQ, EK, X1, e_idx, X2, Me);

    // 6) X3[b] = d0[b]^T @ X2[b]   (4096 x 12288 x 256)
    {
        dim3 g(Nv / 64, 1, Bsz);
        gemm_bf16s<true><<<g, 256>>>(d0, X2, X3, Me, Nv,
                                     (long long)Me * Nv, (long long)Me * 256, (long long)Nv * 256);
    }

    // 7) out = sparse_attention(X3, VK, VQ, v_idx)  -> (B, N, 256)
    sattn_k<<<dim3(Nv, Bsz), 256>>>(VK, VQ, X3, v_idx, out, Nv);
}

// round 7
// speedup vs baseline: 2.3741x; 1.2629x over previous
#include <cuda_runtime.h>
#include <cuda_bf16.h>
#include <cuda_fp16.h>

#define Bsz 2
#define Nv  4096
#define Me  12288

// ---- scratch layout (floats) ----
#define OFF_WT 0LL               // 5 * 65536
#define OFF_VQ 327680LL          // 2*4096*256 each (VQ,VK,VV contiguous)
#define OFF_VK 2424832LL
#define OFF_VV 4521984LL
#define OFF_EQ 6619136LL         // 2*12288*256 each (EQ,EK contiguous)
#define OFF_EK 12910592LL
#define OFF_X1 19202048LL
#define OFF_X2 25493504LL
#define OFF_X3 31784960LL
__device__ float g_scratch[33882112];

// ---------------- low-level helpers ----------------
__device__ __forceinline__ unsigned cvta_s(const void* p) {
    return (unsigned)__cvta_generic_to_shared(p);
}
__device__ __forceinline__ void ldm_x4(unsigned* r, unsigned addr) {
    asm volatile("ldmatrix.sync.aligned.m8n8.x4.shared.b16 {%0,%1,%2,%3},[%4];"
                 : "=r"(r[0]), "=r"(r[1]), "=r"(r[2]), "=r"(r[3]) : "r"(addr));
}
__device__ __forceinline__ void ldm_x4_t(unsigned* r, unsigned addr) {
    asm volatile("ldmatrix.sync.aligned.m8n8.x4.trans.shared.b16 {%0,%1,%2,%3},[%4];"
                 : "=r"(r[0]), "=r"(r[1]), "=r"(r[2]), "=r"(r[3]) : "r"(addr));
}
__device__ __forceinline__ void mma16h(float* c, const unsigned* a, const unsigned* b) {
    asm volatile(
        "mma.sync.aligned.m16n8k16.row.col.f32.f16.f16.f32 "
        "{%0,%1,%2,%3},{%4,%5,%6,%7},{%8,%9},{%0,%1,%2,%3};\n"
        : "+f"(c[0]), "+f"(c[1]), "+f"(c[2]), "+f"(c[3])
        : "r"(a[0]), "r"(a[1]), "r"(a[2]), "r"(a[3]), "r"(b[0]), "r"(b[1]));
}
__device__ __forceinline__ uint2 pack_h4(float4 v) {
    __half2 h0 = __floats2half2_rn(v.x, v.y);
    __half2 h1 = __floats2half2_rn(v.z, v.w);
    uint2 r;
    r.x = *(unsigned*)&h0;
    r.y = *(unsigned*)&h1;
    return r;
}

// ---------------- 256x256 transpose: Wt[d][e] = W[e][d] ----------------
__global__ void transpose256(const float* __restrict__ W, float* __restrict__ Wt) {
    __shared__ float t[32][33];
    int bx = blockIdx.x * 32, by = blockIdx.y * 32;
    int tx = threadIdx.x, ty = threadIdx.y;
#pragma unroll
    for (int j = 0; j < 32; j += 8) t[ty + j][tx] = W[(by + ty + j) * 256 + bx + tx];
    __syncthreads();
#pragma unroll
    for (int j = 0; j < 32; j += 8) Wt[(bx + ty + j) * 256 + by + tx] = t[tx][ty + j];
}

// ---------------- GEMM: C[Mr x 256] = op(A)[Mr x K] @ Bm[K x 256] ----------------
// fp16 operands, fp32 accumulate. Tile 64 x 256 x 16, double-buffered.
// TRANSA=0: A(i,k)=A[i*lda+k]; TRANSA=1: A(i,k)=A[k*lda+i].
// blockIdx.y selects (Bm, C) pair via sBy/sCy strides (batched projections).
template <bool TRANSA>
__global__ void __launch_bounds__(256, 2) gemm_f16(
    const float* __restrict__ A, const float* __restrict__ Bm, float* __restrict__ C,
    int K, int lda, long long sA, long long sB, long long sC,
    long long sBy, long long sCy)
{
    constexpr int A_SZ = 1536;       // halves per A buffer (max of both layouts)
    constexpr int B_SZ = 16 * 264;   // halves per B buffer
    __shared__ __align__(16) __half Ah[2][A_SZ];
    __shared__ __align__(16) __half Bh[2][B_SZ];

    const int bm = blockIdx.x * 64;
    A  += (long long)blockIdx.z * sA;
    Bm += (long long)blockIdx.z * sB + (long long)blockIdx.y * sBy;
    C  += (long long)blockIdx.z * sC + (long long)blockIdx.y * sCy;

    const int tid = threadIdx.x, warp = tid >> 5, lane = tid & 31;
    const int g = lane >> 2, t = lane & 3;
    const int wm = (warp & 1) * 32, wn = (warp >> 1) * 64;
    const int o = lane >> 3, i8 = lane & 7;

    // ldmatrix byte offsets within a buffer
    int offA0;
    if (!TRANSA) {
        // As[m][24 halves]
        int row = wm + ((o & 1) << 3) + i8;
        int col = (o >> 1) << 3;
        offA0 = row * 48 + col * 2;            // mt step = 16 rows = 768 B
    } else {
        // As[k][72 halves]
        int k = ((o >> 1) << 3) + i8;
        int m = wm + ((o & 1) << 3);
        offA0 = k * 144 + m * 2;               // mt step = 16 halves = 32 B
    }
    const int offB0 = (((o & 1) << 3) + i8) * 528 + (wn + ((o >> 1) << 3)) * 2; // np step 32 B

    const unsigned baseA = cvta_s(Ah);
    const unsigned baseB = cvta_s(Bh);

    float acc[2][8][4];
#pragma unroll
    for (int a = 0; a < 2; a++)
#pragma unroll
        for (int b = 0; b < 8; b++)
#pragma unroll
            for (int c = 0; c < 4; c++) acc[a][b][c] = 0.f;

    // staging registers
    float4 ra, rb0, rb1, rb2, rb3;
    const int am = tid >> 2, akq = tid & 3;     // !TRANSA A indexing
    const int ak = tid >> 4, ai4 = tid & 15;    // TRANSA A indexing
    const int bk = tid >> 6, bn4 = tid & 63;    // B indexing

    auto ldg_tile = [&](int kk) {
        if (!TRANSA)
            ra = *(const float4*)(A + (long long)(bm + am) * lda + kk + 4 * akq);
        else
            ra = *(const float4*)(A + (long long)(kk + ak) * lda + bm + 4 * ai4);
        const float* bp = Bm + (long long)kk * 256 + 4 * bn4;
        rb0 = *(const float4*)(bp + (long long)(bk)      * 256);
        rb1 = *(const float4*)(bp + (long long)(bk + 4)  * 256);
        rb2 = *(const float4*)(bp + (long long)(bk + 8)  * 256);
        rb3 = *(const float4*)(bp + (long long)(bk + 12) * 256);
    };
    auto sts_tile = [&](int buf) {
        if (!TRANSA)
            *(uint2*)&Ah[buf][am * 24 + 4 * akq] = pack_h4(ra);
        else
            *(uint2*)&Ah[buf][ak * 72 + 4 * ai4] = pack_h4(ra);
        *(uint2*)&Bh[buf][(bk)      * 264 + 4 * bn4] = pack_h4(rb0);
        *(uint2*)&Bh[buf][(bk + 4)  * 264 + 4 * bn4] = pack_h4(rb1);
        *(uint2*)&Bh[buf][(bk + 8)  * 264 + 4 * bn4] = pack_h4(rb2);
        *(uint2*)&Bh[buf][(bk + 12) * 264 + 4 * bn4] = pack_h4(rb3);
    };

    const int KT = K >> 4;
    ldg_tile(0);
    sts_tile(0);
    __syncthreads();

    int buf = 0;
    for (int kt = 0; kt < KT; kt++) {
        if (kt + 1 < KT) ldg_tile((kt + 1) << 4);

        const unsigned aoffs = buf * (A_SZ * 2);
        const unsigned boffs = buf * (B_SZ * 2);
        unsigned Ar[2][4];
#pragma unroll
        for (int mt = 0; mt < 2; mt++) {
            const int mstep = TRANSA ? 32 : 768;
            if (!TRANSA) ldm_x4(Ar[mt], baseA + aoffs + offA0 + mt * mstep);
            else         ldm_x4_t(Ar[mt], baseA + aoffs + offA0 + mt * mstep);
        }
#pragma unroll
        for (int np = 0; np < 4; np++) {
            unsigned br[4];
            ldm_x4_t(br, baseB + boffs + offB0 + np * 32);
#pragma unroll
            for (int mt = 0; mt < 2; mt++)
#pragma unroll
                for (int j = 0; j < 2; j++)
                    mma16h(acc[mt][2 * np + j], Ar[mt], br + 2 * j);
        }

        if (kt + 1 < KT) sts_tile(buf ^ 1);
        __syncthreads();
        buf ^= 1;
    }

    // epilogue
#pragma unroll
    for (int mt = 0; mt < 2; mt++) {
        int row0 = bm + wm + mt * 16 + g;
#pragma unroll
        for (int nt = 0; nt < 8; nt++) {
            int col = wn + nt * 8 + 2 * t;
            float2 v0 = make_float2(acc[mt][nt][0], acc[mt][nt][1]);
            float2 v1 = make_float2(acc[mt][nt][2], acc[mt][nt][3]);
            *(float2*)(C + (long long)row0 * 256 + col) = v0;
            *(float2*)(C + (long long)(row0 + 8) * 256 + col) = v1;
        }
    }
}

// ---------------- per-head (32-dim) LayerNorm, in place ----------------
__global__ void ln_k(float* __restrict__ X) {
    long long row = blockIdx.x;
    int tx = threadIdx.x;
    float v = X[row * 256 + tx];
    float s = v;
#pragma unroll
    for (int o = 16; o; o >>= 1) s += __shfl_xor_sync(0xffffffffu, s, o);
    float mu = s * (1.f / 32.f);
    float d = v - mu;
    float q = d * d;
#pragma unroll
    for (int o = 16; o; o >>= 1) q += __shfl_xor_sync(0xffffffffu, q, o);
    X[row * 256 + tx] = d * rsqrtf(q * (1.f / 32.f) + 1e-5f);
}

// ---------------- sparse attention ----------------
__global__ void sattn_k(const float* __restrict__ q, const float* __restrict__ k,
                        const float* __restrict__ x, const int* __restrict__ idx,
                        float* __restrict__ out, int R)
{
    int r = blockIdx.x;
    long long boff = (long long)blockIdx.y * R * 256;
    int h = threadIdx.x >> 5, lane = threadIdx.x & 31;
    __shared__ int sidx[16];
    if (threadIdx.x < 16) sidx[threadIdx.x] = idx[r * 16 + threadIdx.x];
    float qv = q[boff + (long long)r * 256 + h * 32 + lane];
    __syncthreads();

    float s[16];
#pragma unroll
    for (int j = 0; j < 16; j++) {
        float p = qv * k[boff + (long long)sidx[j] * 256 + h * 32 + lane];
#pragma unroll
        for (int o = 16; o; o >>= 1) p += __shfl_xor_sync(0xffffffffu, p, o);
        s[j] = p * 0.17677669529663687f;  // 1/sqrt(32)
    }
    float mx = s[0];
#pragma unroll
    for (int j = 1; j < 16; j++) mx = fmaxf(mx, s[j]);
    float se = 0.f;
#pragma unroll
    for (int j = 0; j < 16; j++) { s[j] = __expf(s[j] - mx); se += s[j]; }
    float inv = 1.f / se;
    float acc = 0.f;
#pragma unroll
    for (int j = 0; j < 16; j++)
        acc += s[j] * x[boff + (long long)sidx[j] * 256 + h * 32 + lane];
    out[boff + (long long)r * 256 + h * 32 + lane] = acc * inv;
}

// ---------------- host ----------------
extern "C" void kernel_launch(void* const* d_in, const int* in_sizes, int n_in,
                              void* d_out, int out_size) {
    const float* x_v = (const float*)d_in[0];
    const float* x_e = (const float*)d_in[1];
    const float* d0  = (const float*)d_in[2];
    const int* v_idx = (const int*)d_in[8];
    const int* e_idx = (const int*)d_in[9];
    float* out = (float*)d_out;

    float* S = nullptr;
    cudaGetSymbolAddress((void**)&S, g_scratch);
    float* WT = S + OFF_WT;
    float* VQ = S + OFF_VQ;
    float* EQ = S + OFF_EQ;
    float* VV = S + OFF_VV;
    float* X1 = S + OFF_X1; float* X2 = S + OFF_X2; float* X3 = S + OFF_X3;

    // 1) transpose the 5 weight matrices
    dim3 tb(32, 8), tg(8, 8);
    for (int i = 0; i < 5; i++)
        transpose256<<<tg, tb>>>((const float*)d_in[3 + i], WT + (long long)i * 65536);

    // 2) projections, batched over blockIdx.y:
    //    V: 3 outputs (VQ,VK,VV contiguous @ stride 2097152), weights WT[0..2]
    //    E: 2 outputs (EQ,EK contiguous @ stride 6291456), weights WT[3..4]
    gemm_f16<false><<<dim3(8192 / 64, 3, 1), 256>>>(
        x_v, WT, VQ, 256, 256, 0, 0, 0, 65536LL, 2097152LL);
    gemm_f16<false><<<dim3(24576 / 64, 2, 1), 256>>>(
        x_e, WT + 3LL * 65536, EQ, 256, 256, 0, 0, 0, 65536LL, 6291456LL);

    // 3) per-head layernorms (VQ+VK contiguous; EQ+EK contiguous)
    ln_k<<<16384, 256>>>(VQ);
    ln_k<<<49152, 256>>>(EQ);

    // 4) X1[b] = d0[b] @ VV[b]   (12288 x 4096 x 256)
    gemm_f16<false><<<dim3(Me / 64, 1, Bsz), 256>>>(
        d0, VV, X1, Nv, Nv,
        (long long)Me * Nv, (long long)Nv * 256, (long long)Me * 256, 0, 0);

    // 5) X2 = sparse_attention(X1, EQ, EK, e_idx)
    sattn_k<<<dim3(Me, Bsz), 256>>>(EQ, S + OFF_EK, X1, e_idx, X2, Me);

    // 6) X3[b] = d0[b]^T @ X2[b]   (4096 x 12288 x 256)
    gemm_f16<true><<<dim3(Nv / 64, 1, Bsz), 256>>>(
        d0, X2, X3, Me, Nv,
        (long long)Me * Nv, (long long)Me * 256, (long long)Nv * 256, 0, 0);

    // 7) out = sparse_attention(X3, VK, VQ, v_idx)  -> (B, N, 256)
    sattn_k<<<dim3(Nv, Bsz), 256>>>(S + OFF_VK, VQ, X3, v_idx, out, Nv);
}

// round 10
// speedup vs baseline: 3.1791x; 1.3391x over previous
#include <cuda_runtime.h>
#include <cuda_fp16.h>

#define Bsz 2
#define Nv  4096
#define Me  12288

// ---- fp32 scratch (floats) ----
#define OFF_WT 0LL
#define OFF_VQ 327680LL
#define OFF_VK 2424832LL
#define OFF_VV 4521984LL
#define OFF_EQ 6619136LL
#define OFF_EK 12910592LL
#define OFF_X1 19202048LL      // X1; later reused (X1+X2 region) as split-K partials
#define OFF_X2 25493504LL
#define OFF_X3 31784960LL
__device__ float g_scratch[33882112];

// ---- fp16 scratch (halves) ----
#define HOFF_D0 0LL            // 2*12288*4096
#define HOFF_VV 100663296LL    // 2*4096*256
#define HOFF_X2 102760448LL    // 2*12288*256
__device__ __half g_half[109051904];

// ---------------- low-level helpers ----------------
__device__ __forceinline__ unsigned cvta_s(const void* p) {
    return (unsigned)__cvta_generic_to_shared(p);
}
__device__ __forceinline__ void ldm_x4(unsigned* r, unsigned addr) {
    asm volatile("ldmatrix.sync.aligned.m8n8.x4.shared.b16 {%0,%1,%2,%3},[%4];"
                 : "=r"(r[0]), "=r"(r[1]), "=r"(r[2]), "=r"(r[3]) : "r"(addr));
}
__device__ __forceinline__ void ldm_x4_t(unsigned* r, unsigned addr) {
    asm volatile("ldmatrix.sync.aligned.m8n8.x4.trans.shared.b16 {%0,%1,%2,%3},[%4];"
                 : "=r"(r[0]), "=r"(r[1]), "=r"(r[2]), "=r"(r[3]) : "r"(addr));
}
__device__ __forceinline__ void mma16h(float* c, const unsigned* a, const unsigned* b) {
    asm volatile(
        "mma.sync.aligned.m16n8k16.row.col.f32.f16.f16.f32 "
        "{%0,%1,%2,%3},{%4,%5,%6,%7},{%8,%9},{%0,%1,%2,%3};\n"
        : "+f"(c[0]), "+f"(c[1]), "+f"(c[2]), "+f"(c[3])
        : "r"(a[0]), "r"(a[1]), "r"(a[2]), "r"(a[3]), "r"(b[0]), "r"(b[1]));
}
__device__ __forceinline__ uint2 pack_h4(float4 v) {
    __half2 h0 = __floats2half2_rn(v.x, v.y);
    __half2 h1 = __floats2half2_rn(v.z, v.w);
    uint2 r;
    r.x = *(unsigned*)&h0;
    r.y = *(unsigned*)&h1;
    return r;
}
__device__ __forceinline__ void cp16(unsigned saddr, const void* g) {
    asm volatile("cp.async.cg.shared.global [%0],[%1],16;" :: "r"(saddr), "l"(g));
}
__device__ __forceinline__ void cp_commit() {
    asm volatile("cp.async.commit_group;");
}
template <int N>
__device__ __forceinline__ void cp_wait() {
    asm volatile("cp.async.wait_group %0;" :: "n"(N));
}

// ---------------- fp32 -> fp16 bulk convert ----------------
__global__ void cvt_f2h(const float4* __restrict__ src, uint2* __restrict__ dst, int n4) {
    for (int i = blockIdx.x * blockDim.x + threadIdx.x; i < n4; i += gridDim.x * blockDim.x)
        dst[i] = pack_h4(src[i]);
}

// ---------------- 5x fused 256x256 transpose: Wt[z][d][e] = W[z][e][d] ----------------
__global__ void transpose256x5(const float* __restrict__ W0, const float* __restrict__ W1,
                               const float* __restrict__ W2, const float* __restrict__ W3,
                               const float* __restrict__ W4, float* __restrict__ Wt) {
    const float* W = blockIdx.z == 0 ? W0 : blockIdx.z == 1 ? W1 :
                     blockIdx.z == 2 ? W2 : blockIdx.z == 3 ? W3 : W4;
    float* O = Wt + (long long)blockIdx.z * 65536;
    __shared__ float t[32][33];
    int bx = blockIdx.x * 32, by = blockIdx.y * 32;
    int tx = threadIdx.x, ty = threadIdx.y;
#pragma unroll
    for (int j = 0; j < 32; j += 8) t[ty + j][tx] = W[(by + ty + j) * 256 + bx + tx];
    __syncthreads();
#pragma unroll
    for (int j = 0; j < 32; j += 8) O[(bx + ty + j) * 256 + by + tx] = t[tx][ty + j];
}

// ---------------- projection GEMM (fp32 in, fp32 out): C = A[Mr x 256] @ Bm[256 x 256] ----
__global__ void __launch_bounds__(256, 2) gemm_f16(
    const float* __restrict__ A, const float* __restrict__ Bm, float* __restrict__ C,
    long long sBy, long long sCy)
{
    constexpr int A_SZ = 1536;
    constexpr int B_SZ = 16 * 264;
    __shared__ __align__(16) __half Ah[2][A_SZ];
    __shared__ __align__(16) __half Bh[2][B_SZ];

    const int bm = blockIdx.x * 64;
    Bm += (long long)blockIdx.y * sBy;
    C  += (long long)blockIdx.y * sCy;

    const int tid = threadIdx.x, warp = tid >> 5, lane = tid & 31;
    const int g = lane >> 2, t = lane & 3;
    const int wm = (warp & 1) * 32, wn = (warp >> 1) * 64;
    const int o = lane >> 3, i8 = lane & 7;

    const int offA0 = (wm + ((o & 1) << 3) + i8) * 48 + (((o >> 1) << 3) << 1);
    const int offB0 = (((o & 1) << 3) + i8) * 528 + ((wn + ((o >> 1) << 3)) << 1);
    const unsigned baseA = cvta_s(Ah), baseB = cvta_s(Bh);

    float acc[2][8][4];
#pragma unroll
    for (int a = 0; a < 2; a++)
#pragma unroll
        for (int b = 0; b < 8; b++)
#pragma unroll
            for (int c = 0; c < 4; c++) acc[a][b][c] = 0.f;

    float4 ra, rb0, rb1, rb2, rb3;
    const int am = tid >> 2, akq = tid & 3;
    const int bk = tid >> 6, bn4 = tid & 63;

    auto ldg_tile = [&](int kk) {
        ra = *(const float4*)(A + (long long)(bm + am) * 256 + kk + 4 * akq);
        const float* bp = Bm + (long long)kk * 256 + 4 * bn4;
        rb0 = *(const float4*)(bp + (long long)(bk)      * 256);
        rb1 = *(const float4*)(bp + (long long)(bk + 4)  * 256);
        rb2 = *(const float4*)(bp + (long long)(bk + 8)  * 256);
        rb3 = *(const float4*)(bp + (long long)(bk + 12) * 256);
    };
    auto sts_tile = [&](int buf) {
        *(uint2*)&Ah[buf][am * 24 + 4 * akq] = pack_h4(ra);
        *(uint2*)&Bh[buf][(bk)      * 264 + 4 * bn4] = pack_h4(rb0);
        *(uint2*)&Bh[buf][(bk + 4)  * 264 + 4 * bn4] = pack_h4(rb1);
        *(uint2*)&Bh[buf][(bk + 8)  * 264 + 4 * bn4] = pack_h4(rb2);
        *(uint2*)&Bh[buf][(bk + 12) * 264 + 4 * bn4] = pack_h4(rb3);
    };

    ldg_tile(0);
    sts_tile(0);
    __syncthreads();

    int buf = 0;
    for (int kt = 0; kt < 16; kt++) {
        if (kt + 1 < 16) ldg_tile((kt + 1) << 4);

        const unsigned aoffs = buf * (A_SZ * 2);
        const unsigned boffs = buf * (B_SZ * 2);
        unsigned Ar[2][4];
#pragma unroll
        for (int mt = 0; mt < 2; mt++)
            ldm_x4(Ar[mt], baseA + aoffs + offA0 + mt * 768);
#pragma unroll
        for (int np = 0; np < 4; np++) {
            unsigned br[4];
            ldm_x4_t(br, baseB + boffs + offB0 + np * 32);
#pragma unroll
            for (int mt = 0; mt < 2; mt++)
#pragma unroll
                for (int j = 0; j < 2; j++)
                    mma16h(acc[mt][2 * np + j], Ar[mt], br + 2 * j);
        }

        if (kt + 1 < 16) sts_tile(buf ^ 1);
        __syncthreads();
        buf ^= 1;
    }

#pragma unroll
    for (int mt = 0; mt < 2; mt++) {
        int row0 = bm + wm + mt * 16 + g;
#pragma unroll
        for (int nt = 0; nt < 8; nt++) {
            int col = wn + nt * 8 + 2 * t;
            *(float2*)(C + (long long)row0 * 256 + col) =
                make_float2(acc[mt][nt][0], acc[mt][nt][1]);
            *(float2*)(C + (long long)(row0 + 8) * 256 + col) =
                make_float2(acc[mt][nt][2], acc[mt][nt][3]);
        }
    }
}

// ---------------- big GEMM: C[.. x 256] = op(A)[.. x K] @ Bm[K x 256] ----------------
// fp16 operands in gmem, cp.async double-buffered, tile 128 x 256 x 16, 512 threads.
// TRANSA=0: A(i,k)=A[i*lda+k]; TRANSA=1: A(i,k)=A[k*lda+i].
template <bool TRANSA>
__global__ void __launch_bounds__(512, 1) gemm_h(
    const __half* __restrict__ A, const __half* __restrict__ Bm, float* __restrict__ C,
    int K, int lda,
    long long sA, long long sB, long long sC,       // blockIdx.z strides
    long long sAy, long long sBy, long long sCy)    // blockIdx.y strides (split-K)
{
    constexpr int ABUF = 3072, BBUF = 4224;  // halves per buffer
    __shared__ __align__(16) __half Ab[2][ABUF];
    __shared__ __align__(16) __half Bb[2][BBUF];

    const int bm = blockIdx.x * 128;
    A  += (long long)blockIdx.z * sA + (long long)blockIdx.y * sAy;
    Bm += (long long)blockIdx.z * sB + (long long)blockIdx.y * sBy;
    C  += (long long)blockIdx.z * sC + (long long)blockIdx.y * sCy;

    const int tid = threadIdx.x, warp = tid >> 5, lane = tid & 31;
    const int g = lane >> 2, t = lane & 3;
    const int wm = (warp & 3) * 32, wn = (warp >> 2) * 64;
    const int o = lane >> 3, i8 = lane & 7;

    int offA0;
    if (!TRANSA) offA0 = (wm + ((o & 1) << 3) + i8) * 48 + (((o >> 1) << 3) << 1);
    else         offA0 = (((o >> 1) << 3) + i8) * 272 + ((wm + ((o & 1) << 3)) << 1);
    const int offB0 = (((o & 1) << 3) + i8) * 528 + ((wn + ((o >> 1) << 3)) << 1);

    const unsigned baseA = cvta_s(Ab), baseB = cvta_s(Bb);

    const int fa_r = tid >> 1, fa_c = tid & 1;   // !TRANSA A fill (tid<256)
    const int ft_k = tid >> 4, ft_c = tid & 15;  // TRANSA  A fill (tid<256)
    const int fb_k = tid >> 5, fb_c = tid & 31;  // B fill (all 512)

    auto issue = [&](int kt, int buf) {
        const int kk = kt << 4;
        if (tid < 256) {
            if (!TRANSA)
                cp16(baseA + buf * (ABUF * 2) + fa_r * 48 + fa_c * 16,
                     A + (long long)(bm + fa_r) * lda + kk + fa_c * 8);
            else
                cp16(baseA + buf * (ABUF * 2) + ft_k * 272 + ft_c * 16,
                     A + (long long)(kk + ft_k) * lda + bm + ft_c * 8);
        }
        cp16(baseB + buf * (BBUF * 2) + fb_k * 528 + fb_c * 16,
             Bm + (long long)(kk + fb_k) * 256 + fb_c * 8);
    };

    float acc[2][8][4];
#pragma unroll
    for (int a = 0; a < 2; a++)
#pragma unroll
        for (int b = 0; b < 8; b++)
#pragma unroll
            for (int c = 0; c < 4; c++) acc[a][b][c] = 0.f;

    const int KT = K >> 4;
    issue(0, 0); cp_commit();
    issue(1, 1); cp_commit();

    int buf = 0;
    for (int kt = 0; kt < KT; kt++) {
        cp_wait<1>();
        __syncthreads();

        const unsigned aof = baseA + buf * (ABUF * 2) + offA0;
        unsigned Ar[2][4];
#pragma unroll
        for (int mt = 0; mt < 2; mt++) {
            if (!TRANSA) ldm_x4(Ar[mt], aof + mt * 768);
            else         ldm_x4_t(Ar[mt], aof + mt * 32);
        }
        const unsigned bof = baseB + buf * (BBUF * 2) + offB0;
#pragma unroll
        for (int np = 0; np < 4; np++) {
            unsigned br[4];
            ldm_x4_t(br, bof + np * 32);
#pragma unroll
            for (int mt = 0; mt < 2; mt++)
#pragma unroll
                for (int j = 0; j < 2; j++)
                    mma16h(acc[mt][2 * np + j], Ar[mt], br + 2 * j);
        }

        __syncthreads();
        if (kt + 2 < KT) issue(kt + 2, buf);
        cp_commit();
        buf ^= 1;
    }

#pragma unroll
    for (int mt = 0; mt < 2; mt++) {
        int row0 = bm + wm + mt * 16 + g;
#pragma unroll
        for (int nt = 0; nt < 8; nt++) {
            int col = wn + nt * 8 + 2 * t;
            *(float2*)(C + (long long)row0 * 256 + col) =
                make_float2(acc[mt][nt][0], acc[mt][nt][1]);
            *(float2*)(C + (long long)(row0 + 8) * 256 + col) =
                make_float2(acc[mt][nt][2], acc[mt][nt][3]);
        }
    }
}

// ---------------- split-K reduce: X3 = P0 + P1 + P2 + P3 ----------------
__global__ void reduce4(const float4* __restrict__ P, float4* __restrict__ X3) {
    const int i = blockIdx.x * 256 + threadIdx.x;   // 524288 float4 total
    const long long st = 524288;
    float4 a = P[i], b = P[i + st], c = P[i + 2 * st], d = P[i + 3 * st];
    X3[i] = make_float4(a.x + b.x + c.x + d.x, a.y + b.y + c.y + d.y,
                        a.z + b.z + c.z + d.z, a.w + b.w + c.w + d.w);
}

// ---------------- per-head (32-dim) LayerNorm, in place ----------------
__global__ void ln_k(float* __restrict__ X) {
    long long row = blockIdx.x;
    int tx = threadIdx.x;
    float v = X[row * 256 + tx];
    float s = v;
#pragma unroll
    for (int o = 16; o; o >>= 1) s += __shfl_xor_sync(0xffffffffu, s, o);
    float mu = s * (1.f / 32.f);
    float d = v - mu;
    float q = d * d;
#pragma unroll
    for (int o = 16; o; o >>= 1) q += __shfl_xor_sync(0xffffffffu, q, o);
    X[row * 256 + tx] = d * rsqrtf(q * (1.f / 32.f) + 1e-5f);
}

// ---------------- sparse attention (templated output type) ----------------
template <typename OT>
__global__ void sattn_k(const float* __restrict__ q, const float* __restrict__ k,
                        const float* __restrict__ x, const int* __restrict__ idx,
                        OT* __restrict__ out, int R)
{
    int r = blockIdx.x;
    long long boff = (long long)blockIdx.y * R * 256;
    int h = threadIdx.x >> 5, lane = threadIdx.x & 31;
    __shared__ int sidx[16];
    if (threadIdx.x < 16) sidx[threadIdx.x] = idx[r * 16 + threadIdx.x];
    float qv = q[boff + (long long)r * 256 + h * 32 + lane];
    __syncthreads();

    float s[16];
#pragma unroll
    for (int j = 0; j < 16; j++) {
        float p = qv * k[boff + (long long)sidx[j] * 256 + h * 32 + lane];
#pragma unroll
        for (int o = 16; o; o >>= 1) p += __shfl_xor_sync(0xffffffffu, p, o);
        s[j] = p * 0.17677669529663687f;  // 1/sqrt(32)
    }
    float mx = s[0];
#pragma unroll
    for (int j = 1; j < 16; j++) mx = fmaxf(mx, s[j]);
    float se = 0.f;
#pragma unroll
    for (int j = 0; j < 16; j++) { s[j] = __expf(s[j] - mx); se += s[j]; }
    float inv = 1.f / se;
    float acc = 0.f;
#pragma unroll
    for (int j = 0; j < 16; j++)
        acc += s[j] * x[boff + (long long)sidx[j] * 256 + h * 32 + lane];
    out[boff + (long long)r * 256 + h * 32 + lane] = (OT)(acc * inv);
}

// ---------------- host ----------------
extern "C" void kernel_launch(void* const* d_in, const int* in_sizes, int n_in,
                              void* d_out, int out_size) {
    const float* x_v = (const float*)d_in[0];
    const float* x_e = (const float*)d_in[1];
    const float* d0  = (const float*)d_in[2];
    const int* v_idx = (const int*)d_in[8];
    const int* e_idx = (const int*)d_in[9];
    float* out = (float*)d_out;

    float* S = nullptr;
    cudaGetSymbolAddress((void**)&S, g_scratch);
    __half* Hf = nullptr;
    cudaGetSymbolAddress((void**)&Hf, g_half);

    float* WT = S + OFF_WT;
    float* VQ = S + OFF_VQ; float* VK = S + OFF_VK; float* VV = S + OFF_VV;
    float* EQ = S + OFF_EQ; float* EK = S + OFF_EK;
    float* X1 = S + OFF_X1; float* X3 = S + OFF_X3;
    float* P  = S + OFF_X1;          // split-K partials overlay X1+X2 region
    __half* Hd0 = Hf + HOFF_D0;
    __half* HVV = Hf + HOFF_VV;
    __half* HX2 = Hf + HOFF_X2;

    // 0) d0 -> fp16 (largest convert, kick off first)
    cvt_f2h<<<8192, 256>>>((const float4*)d0, (uint2*)Hd0, 25165824);

    // 1) transpose the 5 weight matrices (one launch)
    transpose256x5<<<dim3(8, 8, 5), dim3(32, 8)>>>(
        (const float*)d_in[3], (const float*)d_in[4], (const float*)d_in[5],
        (const float*)d_in[6], (const float*)d_in[7], WT);

    // 2) projections, batched over blockIdx.y
    gemm_f16<<<dim3(128, 3), 256>>>(x_v, WT, VQ, 65536LL, 2097152LL);
    gemm_f16<<<dim3(384, 2), 256>>>(x_e, WT + 3LL * 65536, EQ, 65536LL, 6291456LL);

    // 2b) VV -> fp16
    cvt_f2h<<<512, 256>>>((const float4*)VV, (uint2*)HVV, 524288);

    // 3) per-head layernorms (VQ+VK contiguous; EQ+EK contiguous)
    ln_k<<<16384, 256>>>(VQ);
    ln_k<<<49152, 256>>>(EQ);

    // 4) X1[b] = d0[b] @ VV[b]   (12288 x 4096 x 256), tile 128x256
    gemm_h<false><<<dim3(Me / 128, 1, Bsz), 512>>>(
        Hd0, HVV, X1, Nv, Nv,
        (long long)Me * Nv, (long long)Nv * 256, (long long)Me * 256, 0, 0, 0);

    // 5) X2h = sparse_attention(X1, EQ, EK, e_idx)  (fp16 output)
    sattn_k<__half><<<dim3(Me, Bsz), 256>>>(EQ, EK, X1, e_idx, HX2, Me);

    // 6) P[y] = d0[b]^T[:, yKc:(y+1)Kc] @ X2h[yKc:(y+1)Kc, :]   split-K=4, Kc=3072
    gemm_h<true><<<dim3(Nv / 128, 4, Bsz), 512>>>(
        Hd0, HX2, P, 3072, Nv,
        (long long)Me * Nv, (long long)Me * 256, (long long)Nv * 256,
        3072LL * Nv, 3072LL * 256, (long long)Bsz * Nv * 256);

    // 6b) X3 = sum of 4 partial slabs
    reduce4<<<2048, 256>>>((const float4*)P, (float4*)X3);

    // 7) out = sparse_attention(X3, VK, VQ, v_idx)  -> (B, N, 256) fp32
    sattn_k<float><<<dim3(Nv, Bsz), 256>>>(VK, VQ, X3, v_idx, out, Nv);
}

// round 12
// speedup vs baseline: 3.7168x; 1.1691x over previous
#include <cuda_runtime.h>
#include <cuda_fp16.h>

#define Bsz 2
#define Nv  4096
#define Me  12288

// ---- fp32 scratch (floats) ----
#define OFF_VQ 327680LL
#define OFF_VK 2424832LL
#define OFF_EQ 6619136LL
#define OFF_EK 12910592LL
#define OFF_X1 19202048LL      // X1; later reused (X1+X2 region) as split-K partials
#define OFF_X3 31784960LL
__device__ float g_scratch[33882112];

// ---- fp16 scratch (halves) ----
#define HOFF_D0 0LL             // 2*12288*4096
#define HOFF_VV 100663296LL     // 2*4096*256
#define HOFF_X2 102760448LL     // 2*12288*256
#define HOFF_XV 109051904LL     // 2*4096*256
#define HOFF_XE 111149056LL     // 2*12288*256
#define HOFF_WT 117440512LL     // 5*65536
__device__ __half g_half[117768192];

// ---------------- low-level helpers ----------------
__device__ __forceinline__ unsigned cvta_s(const void* p) {
    return (unsigned)__cvta_generic_to_shared(p);
}
__device__ __forceinline__ void ldm_x4(unsigned* r, unsigned addr) {
    asm volatile("ldmatrix.sync.aligned.m8n8.x4.shared.b16 {%0,%1,%2,%3},[%4];"
                 : "=r"(r[0]), "=r"(r[1]), "=r"(r[2]), "=r"(r[3]) : "r"(addr));
}
__device__ __forceinline__ void ldm_x4_t(unsigned* r, unsigned addr) {
    asm volatile("ldmatrix.sync.aligned.m8n8.x4.trans.shared.b16 {%0,%1,%2,%3},[%4];"
                 : "=r"(r[0]), "=r"(r[1]), "=r"(r[2]), "=r"(r[3]) : "r"(addr));
}
__device__ __forceinline__ void mma16h(float* c, const unsigned* a, const unsigned* b) {
    asm volatile(
        "mma.sync.aligned.m16n8k16.row.col.f32.f16.f16.f32 "
        "{%0,%1,%2,%3},{%4,%5,%6,%7},{%8,%9},{%0,%1,%2,%3};\n"
        : "+f"(c[0]), "+f"(c[1]), "+f"(c[2]), "+f"(c[3])
        : "r"(a[0]), "r"(a[1]), "r"(a[2]), "r"(a[3]), "r"(b[0]), "r"(b[1]));
}
__device__ __forceinline__ uint2 pack_h4(float4 v) {
    __half2 h0 = __floats2half2_rn(v.x, v.y);
    __half2 h1 = __floats2half2_rn(v.z, v.w);
    uint2 r;
    r.x = *(unsigned*)&h0;
    r.y = *(unsigned*)&h1;
    return r;
}
__device__ __forceinline__ void cp16(unsigned saddr, const void* g) {
    asm volatile("cp.async.cg.shared.global [%0],[%1],16;" :: "r"(saddr), "l"(g));
}
__device__ __forceinline__ void cp_commit() {
    asm volatile("cp.async.commit_group;");
}
template <int N>
__device__ __forceinline__ void cp_wait() {
    asm volatile("cp.async.wait_group %0;" :: "n"(N));
}

// ---------------- fp32 -> fp16 bulk convert ----------------
__global__ void cvt_f2h(const float4* __restrict__ src, uint2* __restrict__ dst, int n4) {
    for (int i = blockIdx.x * blockDim.x + threadIdx.x; i < n4; i += gridDim.x * blockDim.x)
        dst[i] = pack_h4(src[i]);
}

// ---------- 5x fused 256x256 transpose -> fp16: Wt[z][d][e] = h(W[z][e][d]) ----------
__global__ void transpose256x5h(const float* __restrict__ W0, const float* __restrict__ W1,
                                const float* __restrict__ W2, const float* __restrict__ W3,
                                const float* __restrict__ W4, __half* __restrict__ Wt) {
    const float* W = blockIdx.z == 0 ? W0 : blockIdx.z == 1 ? W1 :
                     blockIdx.z == 2 ? W2 : blockIdx.z == 3 ? W3 : W4;
    __half* O = Wt + (long long)blockIdx.z * 65536;
    __shared__ float t[32][33];
    int bx = blockIdx.x * 32, by = blockIdx.y * 32;
    int tx = threadIdx.x, ty = threadIdx.y;
#pragma unroll
    for (int j = 0; j < 32; j += 8) t[ty + j][tx] = W[(by + ty + j) * 256 + bx + tx];
    __syncthreads();
#pragma unroll
    for (int j = 0; j < 32; j += 8)
        O[(bx + ty + j) * 256 + by + tx] = __float2half_rn(t[tx][ty + j]);
}

// ---------------- GEMM: C[.. x 256] = op(A)[.. x K] @ Bm[K x 256] ----------------
// fp16 operands in gmem, 4-stage cp.async pipeline, tile 128 x 256 x 16, 512 thr.
// TRANSA=0: A(i,k)=A[i*lda+k]; TRANSA=1: A(i,k)=A[k*lda+i]. OutT = float or __half.
template <bool TRANSA, typename OutT>
__global__ void __launch_bounds__(512, 1) gemm_h(
    const __half* __restrict__ A, const __half* __restrict__ Bm, OutT* __restrict__ C,
    int K, int lda,
    long long sA, long long sB, long long sC,       // blockIdx.z strides
    long long sAy, long long sBy, long long sCy)    // blockIdx.y strides
{
    constexpr int S = 4;
    constexpr int A_STG = 3072;       // halves per A stage (128*24; TRANSA uses 16*136)
    constexpr int B_STG = 4224;       // halves per B stage (16*264)
    __shared__ __align__(16) __half Ab[S * A_STG];
    __shared__ __align__(16) __half Bb[S * B_STG];

    const int bm = blockIdx.x * 128;
    A  += (long long)blockIdx.z * sA + (long long)blockIdx.y * sAy;
    Bm += (long long)blockIdx.z * sB + (long long)blockIdx.y * sBy;
    C  += (long long)blockIdx.z * sC + (long long)blockIdx.y * sCy;

    const int tid = threadIdx.x, warp = tid >> 5, lane = tid & 31;
    const int g = lane >> 2, t = lane & 3;
    const int wm = (warp & 3) * 32, wn = (warp >> 2) * 64;
    const int o = lane >> 3, i8 = lane & 7;

    int offA0;
    if (!TRANSA) offA0 = (wm + ((o & 1) << 3) + i8) * 48 + (((o >> 1) << 3) << 1);
    else         offA0 = (((o >> 1) << 3) + i8) * 272 + ((wm + ((o & 1) << 3)) << 1);
    const int offB0 = (((o & 1) << 3) + i8) * 528 + ((wn + ((o >> 1) << 3)) << 1);

    const unsigned baseA = cvta_s(Ab), baseB = cvta_s(Bb);

    const int fa_r = tid >> 1, fa_c = tid & 1;   // !TRANSA A fill (tid<256)
    const int ft_k = tid >> 4, ft_c = tid & 15;  // TRANSA  A fill (tid<256)
    const int fb_k = tid >> 5, fb_c = tid & 31;  // B fill (all 512)

    auto issue = [&](int kt, int buf) {
        const int kk = kt << 4;
        if (tid < 256) {
            if (!TRANSA)
                cp16(baseA + buf * (A_STG * 2) + fa_r * 48 + fa_c * 16,
                     A + (long long)(bm + fa_r) * lda + kk + fa_c * 8);
            else
                cp16(baseA + buf * (A_STG * 2) + ft_k * 272 + ft_c * 16,
                     A + (long long)(kk + ft_k) * lda + bm + ft_c * 8);
        }
        cp16(baseB + buf * (B_STG * 2) + fb_k * 528 + fb_c * 16,
             Bm + (long long)(kk + fb_k) * 256 + fb_c * 8);
    };

    float acc[2][8][4];
#pragma unroll
    for (int a = 0; a < 2; a++)
#pragma unroll
        for (int b = 0; b < 8; b++)
#pragma unroll
            for (int c = 0; c < 4; c++) acc[a][b][c] = 0.f;

    const int KT = K >> 4;
    issue(0, 0); cp_commit();
    issue(1, 1); cp_commit();
    issue(2, 2); cp_commit();

    for (int kt = 0; kt < KT; kt++) {
        const int buf = kt & 3;
        cp_wait<2>();
        __syncthreads();

        // prefetch all fragments for this tile
        const unsigned aof = baseA + buf * (A_STG * 2) + offA0;
        const unsigned bof = baseB + buf * (B_STG * 2) + offB0;
        unsigned Ar[2][4], Br[4][4];
#pragma unroll
        for (int mt = 0; mt < 2; mt++) {
            if (!TRANSA) ldm_x4(Ar[mt], aof + mt * 768);
            else         ldm_x4_t(Ar[mt], aof + mt * 32);
        }
#pragma unroll
        for (int np = 0; np < 4; np++)
            ldm_x4_t(Br[np], bof + np * 32);

        // pure mma burst
#pragma unroll
        for (int np = 0; np < 4; np++)
#pragma unroll
            for (int mt = 0; mt < 2; mt++)
#pragma unroll
                for (int j = 0; j < 2; j++)
                    mma16h(acc[mt][2 * np + j], Ar[mt], Br[np] + 2 * j);

        if (kt + 3 < KT) issue(kt + 3, (kt + 3) & 3);
        cp_commit();
    }

    // epilogue
#pragma unroll
    for (int mt = 0; mt < 2; mt++) {
        int row0 = bm + wm + mt * 16 + g;
#pragma unroll
        for (int nt = 0; nt < 8; nt++) {
            int col = wn + nt * 8 + 2 * t;
            if (sizeof(OutT) == 4) {
                float* Cf = (float*)C;
                *(float2*)(Cf + (long long)row0 * 256 + col) =
                    make_float2(acc[mt][nt][0], acc[mt][nt][1]);
                *(float2*)(Cf + (long long)(row0 + 8) * 256 + col) =
                    make_float2(acc[mt][nt][2], acc[mt][nt][3]);
            } else {
                __half* Ch = (__half*)C;
                __half2 h0 = __floats2half2_rn(acc[mt][nt][0], acc[mt][nt][1]);
                __half2 h1 = __floats2half2_rn(acc[mt][nt][2], acc[mt][nt][3]);
                *(__half2*)(Ch + (long long)row0 * 256 + col) = h0;
                *(__half2*)(Ch + (long long)(row0 + 8) * 256 + col) = h1;
            }
        }
    }
}

// ---------------- split-K reduce: X3 = P0 + P1 + P2 + P3 ----------------
__global__ void reduce4(const float4* __restrict__ P, float4* __restrict__ X3) {
    const int i = blockIdx.x * 256 + threadIdx.x;   // 524288 float4 total
    const long long st = 524288;
    float4 a = P[i], b = P[i + st], c = P[i + 2 * st], d = P[i + 3 * st];
    X3[i] = make_float4(a.x + b.x + c.x + d.x, a.y + b.y + c.y + d.y,
                        a.z + b.z + c.z + d.z, a.w + b.w + c.w + d.w);
}

// ---------------- per-head (32-dim) LayerNorm, in place ----------------
__global__ void ln_k(float* __restrict__ X) {
    long long row = blockIdx.x;
    int tx = threadIdx.x;
    float v = X[row * 256 + tx];
    float s = v;
#pragma unroll
    for (int o = 16; o; o >>= 1) s += __shfl_xor_sync(0xffffffffu, s, o);
    float mu = s * (1.f / 32.f);
    float d = v - mu;
    float q = d * d;
#pragma unroll
    for (int o = 16; o; o >>= 1) q += __shfl_xor_sync(0xffffffffu, q, o);
    X[row * 256 + tx] = d * rsqrtf(q * (1.f / 32.f) + 1e-5f);
}

// ---------------- sparse attention (templated output type) ----------------
template <typename OT>
__global__ void sattn_k(const float* __restrict__ q, const float* __restrict__ k,
                        const float* __restrict__ x, const int* __restrict__ idx,
                        OT* __restrict__ out, int R)
{
    int r = blockIdx.x;
    long long boff = (long long)blockIdx.y * R * 256;
    int h = threadIdx.x >> 5, lane = threadIdx.x & 31;
    __shared__ int sidx[16];
    if (threadIdx.x < 16) sidx[threadIdx.x] = idx[r * 16 + threadIdx.x];
    float qv = q[boff + (long long)r * 256 + h * 32 + lane];
    __syncthreads();

    float s[16];
#pragma unroll
    for (int j = 0; j < 16; j++) {
        float p = qv * k[boff + (long long)sidx[j] * 256 + h * 32 + lane];
#pragma unroll
        for (int o = 16; o; o >>= 1) p += __shfl_xor_sync(0xffffffffu, p, o);
        s[j] = p * 0.17677669529663687f;  // 1/sqrt(32)
    }
    float mx = s[0];
#pragma unroll
    for (int j = 1; j < 16; j++) mx = fmaxf(mx, s[j]);
    float se = 0.f;
#pragma unroll
    for (int j = 0; j < 16; j++) { s[j] = __expf(s[j] - mx); se += s[j]; }
    float inv = 1.f / se;
    float acc = 0.f;
#pragma unroll
    for (int j = 0; j < 16; j++)
        acc += s[j] * x[boff + (long long)sidx[j] * 256 + h * 32 + lane];
    out[boff + (long long)r * 256 + h * 32 + lane] = (OT)(acc * inv);
}

// ---------------- host ----------------
extern "C" void kernel_launch(void* const* d_in, const int* in_sizes, int n_in,
                              void* d_out, int out_size) {
    const float* x_v = (const float*)d_in[0];
    const float* x_e = (const float*)d_in[1];
    const float* d0  = (const float*)d_in[2];
    const int* v_idx = (const int*)d_in[8];
    const int* e_idx = (const int*)d_in[9];
    float* out = (float*)d_out;

    float* S = nullptr;
    cudaGetSymbolAddress((void**)&S, g_scratch);
    __half* Hf = nullptr;
    cudaGetSymbolAddress((void**)&Hf, g_half);

    float* VQ = S + OFF_VQ; float* VK = S + OFF_VK;
    float* EQ = S + OFF_EQ; float* EK = S + OFF_EK;
    float* X1 = S + OFF_X1; float* X3 = S + OFF_X3;
    float* P  = S + OFF_X1;          // split-K partials overlay X1/X2 region
    __half* Hd0 = Hf + HOFF_D0;
    __half* HVV = Hf + HOFF_VV;
    __half* HX2 = Hf + HOFF_X2;
    __half* Hxv = Hf + HOFF_XV;
    __half* Hxe = Hf + HOFF_XE;
    __half* HWT = Hf + HOFF_WT;

    // 0) inputs -> fp16
    cvt_f2h<<<2048, 256>>>((const float4*)x_v, (uint2*)Hxv, 524288);
    cvt_f2h<<<6144, 256>>>((const float4*)x_e, (uint2*)Hxe, 1572864);
    cvt_f2h<<<8192, 256>>>((const float4*)d0, (uint2*)Hd0, 25165824);

    // 1) transpose weights -> fp16 (one launch)
    transpose256x5h<<<dim3(8, 8, 5), dim3(32, 8)>>>(
        (const float*)d_in[3], (const float*)d_in[4], (const float*)d_in[5],
        (const float*)d_in[6], (const float*)d_in[7], HWT);

    // 2) projections (async GEMM); VV written directly as fp16
    gemm_h<false, float><<<dim3(64, 2, 1), 512>>>(
        Hxv, HWT, VQ, 256, 256, 0, 0, 0, 0, 65536LL, 2097152LL);
    gemm_h<false, __half><<<dim3(64, 1, 1), 512>>>(
        Hxv, HWT + 2LL * 65536, HVV, 256, 256, 0, 0, 0, 0, 0, 0);
    gemm_h<false, float><<<dim3(192, 2, 1), 512>>>(
        Hxe, HWT + 3LL * 65536, EQ, 256, 256, 0, 0, 0, 0, 65536LL, 6291456LL);

    // 3) per-head layernorms (VQ+VK contiguous; EQ+EK contiguous)
    ln_k<<<16384, 256>>>(VQ);
    ln_k<<<49152, 256>>>(EQ);

    // 4) X1[b] = d0[b] @ VV[b]   (12288 x 4096 x 256)
    gemm_h<false, float><<<dim3(Me / 128, 1, Bsz), 512>>>(
        Hd0, HVV, X1, Nv, Nv,
        (long long)Me * Nv, (long long)Nv * 256, (long long)Me * 256, 0, 0, 0);

    // 5) X2h = sparse_attention(X1, EQ, EK, e_idx)  (fp16 output)
    sattn_k<__half><<<dim3(Me, Bsz), 256>>>(EQ, EK, X1, e_idx, HX2, Me);

    // 6) P[y] = d0[b]^T[:, yKc:(y+1)Kc] @ X2h[yKc:(y+1)Kc, :]   split-K=4, Kc=3072
    gemm_h<true, float><<<dim3(Nv / 128, 4, Bsz), 512>>>(
        Hd0, HX2, P, 3072, Nv,
        (long long)Me * Nv, (long long)Me * 256, (long long)Nv * 256,
        3072LL * Nv, 3072LL * 256, (long long)Bsz * Nv * 256);

    // 6b) X3 = sum of 4 partial slabs
    reduce4<<<2048, 256>>>((const float4*)P, (float4*)X3);

    // 7) out = sparse_attention(X3, VK, VQ, v_idx)  -> (B, N, 256) fp32
    sattn_k<float><<<dim3(Nv, Bsz), 256>>>(VK, VQ, X3, v_idx, out, Nv);
}